// round 16
// baseline (speedup 1.0000x reference)
#include <cuda_runtime.h>
#include <math.h>
#include <stdint.h>

#define NB    4
#define LSEQ  2054
#define LSEQT 2080
#define EE    512
#define HID   640
#define NHh   10
#define NC    527
#define MH    20
#define MHH   10          // heads per m-half
#define SNT   64
#define SNB   33
#define ETIL  16
#define NTIL  9
#define FEAT_BLKS (ETIL*NTIL*NB)   // 576
#define GRIDT (SNB*NB)             // 132 tail blocks, 1/SM (proven safe)
#define TTHR  1024
#define HSM   28160                // per-half smem slice

typedef unsigned long long u64;

// ---------------- device scratch ----------------
__device__ __align__(128) float2 g_ft2[NB*256*LSEQT];
__device__ u64   g_kq2[NB*256*MH];
__device__ float g_cb[NB*MH];
__device__ float g_mx  [SNB*NB*MH];
__device__ float g_denp[SNB*NB*MH];
__device__ float g_wfp [SNB*NB*MH*EE];
__device__ float g_pp[8*8*HID];            // (es8, bm, col)
__device__ unsigned g_barc = 0;
__device__ volatile unsigned g_gen = 0;

// ---------------- grid barrier (132 blocks, 1/SM => always co-resident) ----
__device__ __forceinline__ void gsync(){
  __syncthreads();
  if (threadIdx.x == 0){
    __threadfence();
    unsigned gen = g_gen;
    unsigned arrived = atomicAdd(&g_barc, 1u) + 1u;
    if (arrived % GRIDT == 0u){
      __threadfence();
      g_gen = gen + 1u;
    } else {
      while (g_gen == gen) { __nanosleep(64); }
    }
    __threadfence();
  }
  __syncthreads();
}

// ---------------- packed f32x2 helpers ----------------
__device__ __forceinline__ u64 pk2(float x, float y){
  u64 r; asm("mov.b64 %0,{%1,%2};" : "=l"(r) : "f"(x), "f"(y)); return r;
}
__device__ __forceinline__ float2 upk2(u64 v){
  float2 r; asm("mov.b64 {%0,%1},%2;" : "=f"(r.x), "=f"(r.y) : "l"(v)); return r;
}
__device__ __forceinline__ void fma2(u64 &d, u64 a, u64 b){
  asm("fma.rn.f32x2 %0,%1,%2,%0;" : "+l"(d) : "l"(a), "l"(b));
}
__device__ __forceinline__ u64 add2(u64 a, u64 b){
  u64 r; asm("add.rn.f32x2 %0,%1,%2;" : "=l"(r) : "l"(a), "l"(b)); return r;
}

__device__ __forceinline__ const float* row_src(int b, int n,
    const float* aud, const float* vid, const float* atok,
    const float* vtok, const float* btk){
  if (n < 1024)  return aud + ((size_t)b*1024 + n)*EE;
  if (n == 1024) return atok;
  if (n < 1029)  return btk + (size_t)(n-1025)*EE;
  if (n < 2053)  return vid + ((size_t)b*1024 + (n-1029))*EE;
  return vtok;
}

__device__ __forceinline__ float pe_val(int n, int e){
  float f = __expf(-(float)(e & ~1) * (9.210340371976184f/512.0f));
  float a = (float)n * f;
  float q = rintf(a * 0.15915494309189535f);
  a = fmaf(q, -6.2831855f, a);
  a = fmaf(q, 1.7484556e-7f, a);
  float sn, cs; __sincosf(a, &sn, &cs);
  return (e & 1) ? cs : sn;
}

// ================ K1: prep = ft2 (rotation recurrence) + kq =======
__global__ void __launch_bounds__(256) k_prep(
    const float* __restrict__ aud, const float* __restrict__ vid,
    const float* __restrict__ atok, const float* __restrict__ vtok,
    const float* __restrict__ btk,
    const float* __restrict__ Wk, const float* __restrict__ bk,
    const float* __restrict__ Wq, const float* __restrict__ bq){
  int blk = blockIdx.x;
  int tid = threadIdx.x;
  if (blk < FEAT_BLKS){
    __shared__ float s_t[256][33];
    int et = blk % ETIL;
    int nt = (blk / ETIL) % NTIL;
    int bz = blk / (ETIL*NTIL);
    int lane = tid & 31, w = tid >> 5;
    int e = et*32 + lane;
    bool odd = e & 1;
    float f = __expf(-(float)(e & ~1) * (9.210340371976184f/512.0f));
    int n0 = nt*256 + w*32;
    float a = (float)n0 * f;
    float qr = rintf(a * 0.15915494309189535f);
    a = fmaf(qr, -6.2831855f, a);
    a = fmaf(qr, 1.7484556e-7f, a);
    float sn, cs; __sincosf(a, &sn, &cs);
    float sf, cf; __sincosf(f, &sf, &cf);
    #pragma unroll 4
    for (int j = 0; j < 32; j++){
      int n = n0 + j;
      float v = 0.f;
      if (n < LSEQ){
        const float* src = row_src(bz, n, aud, vid, atok, vtok, btk);
        v = src[e] + (odd ? cs : sn);
      }
      s_t[w*32 + j][lane] = v;
      float sn2 = fmaf(sn, cf,  cs*sf);
      float cs2 = fmaf(cs, cf, -sn*sf);
      sn = sn2; cs = cs2;
    }
    __syncthreads();
    for (int pe = w; pe < 16; pe += 8){
      #pragma unroll
      for (int k = 0; k < 8; k++){
        int nl = lane + 32*k;
        int n = nt*256 + nl;
        if (n < LSEQ){
          float2 v2 = make_float2(s_t[nl][2*pe], s_t[nl][2*pe+1]);
          g_ft2[((size_t)bz*256 + et*16 + pe)*LSEQT + n] = v2;
        }
      }
    }
  } else {
    __shared__ float sf[EE];
    __shared__ float spart[4][64];
    __shared__ float kk[64];
    int blk2 = blk - FEAT_BLKS;
    int b = blk2 / MH, mh = blk2 % MH, m = mh / NHh, h = mh % NHh;
    int nrow = m ? 1029 : 0;
    const float* src = m ? (vid + (size_t)b*1024*EE) : (aud + (size_t)b*1024*EE);
    for (int e = tid; e < EE; e += 256)
      sf[e] = src[e] + pe_val(nrow, e);
    __syncthreads();
    {
      int col = tid & 63, eg = tid >> 6;
      const float* w = Wk + h*64 + col;
      float p = 0.f;
      #pragma unroll 4
      for (int e = eg*128; e < eg*128 + 128; e++)
        p = fmaf(sf[e], w[(size_t)e*HID], p);
      spart[eg][col] = p;
    }
    __syncthreads();
    if (tid < 64)
      kk[tid] = bk[h*64 + tid] + ((spart[0][tid] + spart[1][tid]) +
                                  (spart[2][tid] + spart[3][tid]));
    __syncthreads();
    if (tid == 0){
      float s2 = 0.f;
      for (int d = 0; d < 64; d++) s2 += kk[d]*bq[h*64 + d];
      g_cb[blk2] = s2;
    }
    int e0 = tid*2;
    const float4* w0 = (const float4*)(Wq + (size_t)e0*HID + h*64);
    const float4* w1 = (const float4*)(Wq + (size_t)(e0+1)*HID + h*64);
    float r0 = 0.f, r1 = 0.f;
    #pragma unroll
    for (int d4 = 0; d4 < 16; d4++){
      float4 a = w0[d4], c = w1[d4];
      float k0 = kk[4*d4], k1 = kk[4*d4+1], k2 = kk[4*d4+2], k3 = kk[4*d4+3];
      r0 = fmaf(k0,a.x, fmaf(k1,a.y, fmaf(k2,a.z, fmaf(k3,a.w, r0))));
      r1 = fmaf(k0,c.x, fmaf(k1,c.y, fmaf(k2,c.z, fmaf(k3,c.w, r1))));
    }
    g_kq2[((size_t)b*256 + tid)*MH + mh] = pk2(r0, r1);
  }
}

// ================ K2: tail (1024 thr, 1 blk/SM, both m-halves) =============
// dyn smem 56,320 B = 2 x 28,160 B half-slices. Per half:
//   [0,20480)      s_kq u64[256][10] -> overlay s_part f[8][64][10] -> s_comb
//   [20480,23040)  s_sc  f[64][10]
//   [23040,28160)  s_p   u64[64][10]
__global__ void __launch_bounds__(TTHR, 1) k_tail(
    const float* __restrict__ Wv,  const float* __restrict__ bv,
    const float* __restrict__ lng, const float* __restrict__ lnb,
    const float* __restrict__ Wap, const float* __restrict__ bap,
    const float* __restrict__ Wvp, const float* __restrict__ bvp,
    float* __restrict__ out){
  extern __shared__ __align__(16) char dyn[];
  int tid = threadIdx.x, blk = blockIdx.x;

  // ======== phase A: attention (132 blocks x 2 m-halves) ========
  {
    int hm = tid >> 9;                 // m half: 0 or 1
    int tid2 = tid & 511;
    char* dynh = dyn + hm*HSM;
    u64*  s_kq = (u64*)dynh;
    float (*s_part)[SNT][MHH] = (float(*)[SNT][MHH])dynh;
    float (*s_sc)[MHH]        = (float(*)[MHH])(dynh + 20480);
    u64   (*s_p)[MHH]         = (u64(*)[MHH])(dynh + 23040);
    u64*  s_comb              = (u64*)dynh;
    __shared__ float s_cb[2][MHH], s_mx[2][MHH];
    int c = blk % SNB, b = blk / SNB;
    int q0 = hm*MHH;
    int nbase = c*SNT;
    {
      const u64* src = g_kq2 + (size_t)b*256*MH + q0;
      for (int i = tid2; i < 256*MHH; i += 512){
        int p = i / MHH, q = i % MHH;
        s_kq[p*MHH + q] = src[(size_t)p*MH + q];
      }
    }
    if (tid2 < MHH) s_cb[hm][tid2] = g_cb[b*MH + q0 + tid2];
    __syncthreads();
    int slot = tid2 & 63, esub = tid2 >> 6;   // esub 0..7 = 32 e-pairs each
    int n = nbase + slot; if (n > LSEQ-1) n = LSEQ-1;
    const float2* ft = g_ft2 + ((size_t)b*256 + esub*32)*LSEQT + n;
    const u64* kqp = s_kq + (size_t)(esub*32)*MHH;
    u64 acc[MHH];
    #pragma unroll
    for (int q = 0; q < MHH; q++) acc[q] = 0ull;
    #pragma unroll 4
    for (int ep = 0; ep < 32; ep++){
      u64 f2 = *(const u64*)(ft + (size_t)ep*LSEQT);
      const ulonglong2* kp2 = (const ulonglong2*)(kqp + (size_t)ep*MHH);
      #pragma unroll
      for (int q2 = 0; q2 < 5; q2++){
        ulonglong2 kk2 = kp2[q2];
        fma2(acc[2*q2  ], f2, kk2.x);
        fma2(acc[2*q2+1], f2, kk2.y);
      }
    }
    __syncthreads();
    #pragma unroll
    for (int q = 0; q < MHH; q++){
      float2 v2 = upk2(acc[q]);
      s_part[esub][slot][q] = v2.x + v2.y;
    }
    __syncthreads();
    for (int i = tid2; i < SNT*MHH; i += 512){
      int nl = i / MHH, q = i % MHH;
      float s = ((s_part[0][nl][q] + s_part[1][nl][q]) +
                 (s_part[2][nl][q] + s_part[3][nl][q])) +
                ((s_part[4][nl][q] + s_part[5][nl][q]) +
                 (s_part[6][nl][q] + s_part[7][nl][q]));
      s = (s + s_cb[hm][q]) * 0.125f;
      s_sc[nl][q] = (nbase + nl < LSEQ) ? s : -1e30f;
    }
    __syncthreads();
    // reduction over 8-token strips: 96 threads = 3 FULL warps (shfl-safe);
    // q >= MHH lanes participate in shuffles on a clamped index, never write.
    if (tid2 < 96){
      int q = tid2 >> 3, j = tid2 & 7;
      int qc = q < MHH ? q : MHH-1;
      float mloc = -1e30f;
      #pragma unroll
      for (int nl = j*8; nl < j*8 + 8; nl++) mloc = fmaxf(mloc, s_sc[nl][qc]);
      mloc = fmaxf(mloc, __shfl_xor_sync(0xffffffffu, mloc, 1));
      mloc = fmaxf(mloc, __shfl_xor_sync(0xffffffffu, mloc, 2));
      mloc = fmaxf(mloc, __shfl_xor_sync(0xffffffffu, mloc, 4));
      if (j == 0 && q < MHH){ s_mx[hm][q] = mloc; g_mx[(c*NB + b)*MH + q0 + q] = mloc; }
    }
    __syncthreads();
    for (int i = tid2; i < SNT*MHH; i += 512){
      int nl = i / MHH, q = i % MHH;
      float p = __expf(s_sc[nl][q] - s_mx[hm][q]);
      s_p[nl][q] = pk2(p, p);
    }
    __syncthreads();
    if (tid2 < 96){
      int q = tid2 >> 3, j = tid2 & 7;
      int qc = q < MHH ? q : MHH-1;
      float d = 0.f;
      #pragma unroll
      for (int nl = j*8; nl < j*8 + 8; nl++) d += *(const float*)&s_p[nl][qc];
      d += __shfl_xor_sync(0xffffffffu, d, 1);
      d += __shfl_xor_sync(0xffffffffu, d, 2);
      d += __shfl_xor_sync(0xffffffffu, d, 4);
      if (j == 0 && q < MHH) g_denp[(c*NB + b)*MH + q0 + q] = d;
    }
    // ---- weighted feats: 2 token-halves x 256 e-pairs per m-half ----
    int half = tid2 >> 8, ep0 = tid2 & 255;
    int nv = LSEQ - nbase; if (nv > SNT) nv = SNT;
    int nlo = half*32;
    int nhi = nv < (half+1)*32 ? nv : (half+1)*32;
    const float2* fb2 = g_ft2 + ((size_t)b*256 + ep0)*LSEQT + nbase;
    u64 acc2[MHH];
    #pragma unroll
    for (int q = 0; q < MHH; q++) acc2[q] = 0ull;
    #pragma unroll 2
    for (int nl = nlo; nl < nhi; nl++){
      u64 f = *(const u64*)(fb2 + nl);
      const ulonglong2* pp2 = (const ulonglong2*)s_p[nl];
      #pragma unroll
      for (int q2 = 0; q2 < 5; q2++){
        ulonglong2 pk = pp2[q2];
        fma2(acc2[2*q2  ], pk.x, f);
        fma2(acc2[2*q2+1], pk.y, f);
      }
    }
    if (half == 1){
      #pragma unroll
      for (int q = 0; q < MHH; q++) s_comb[ep0*MHH + q] = acc2[q];
    }
    __syncthreads();
    if (half == 0){
      float* dst = g_wfp + ((size_t)(c*NB + b)*MH + q0)*EE + ep0*2;
      #pragma unroll
      for (int q = 0; q < MHH; q++){
        float2 v2 = upk2(add2(acc2[q], s_comb[ep0*MHH + q]));
        *(float2*)(dst + (size_t)q*EE) = v2;
      }
    }
  }

  gsync();

  // ======== phase B: flash-combine + partial Wv proj (blocks 0..63) ========
  if (blk < 64){
    float (*s_mxp)[SNB+1]   = (float(*)[SNB+1])dyn;
    float (*s_scale)[SNB+1] = (float(*)[SNB+1])(dyn + 1360);
    float* s_m   = (float*)(dyn + 2720);
    float* s_inv = (float*)(dyn + 2784);
    float (*s_wf)[64] = (float(*)[64])(dyn + 2848);     // [10][64]
    int bm = blk >> 3, es = blk & 7;                    // 8 e-slices of 64
    int b = bm >> 1, m = bm & 1, q0 = m*NHh;
    for (int i = tid; i < NHh*SNB; i += TTHR){
      int h = i / SNB, cc = i % SNB;
      s_mxp[h][cc] = g_mx[(cc*NB + b)*MH + q0 + h];
    }
    __syncthreads();
    if (tid < NHh){
      float mm = -1e30f;
      for (int cc = 0; cc < SNB; cc++) mm = fmaxf(mm, s_mxp[tid][cc]);
      s_m[tid] = mm;
    }
    __syncthreads();
    for (int i = tid; i < NHh*SNB; i += TTHR){
      int h = i / SNB, cc = i % SNB;
      s_scale[h][cc] = __expf(s_mxp[h][cc] - s_m[h]);
    }
    __syncthreads();
    if (tid < NHh){
      float dd = 0.f;
      for (int cc = 0; cc < SNB; cc++)
        dd += g_denp[(cc*NB + b)*MH + q0 + tid] * s_scale[tid][cc];
      s_inv[tid] = 1.f/dd;
    }
    __syncthreads();
    if (tid < 320){                         // (h, e-pair) over 64-e slice
      int h = tid >> 5, ep = tid & 31;
      const float* base = g_wfp + (size_t)(q0 + h)*EE + es*64 + ep*2;
      float a0 = 0.f, a1 = 0.f;
      #pragma unroll 3
      for (int cc = 0; cc < SNB; cc++){
        float sc = s_scale[h][cc];
        float2 v2 = *(const float2*)(base + (size_t)(cc*NB + b)*MH*EE);
        a0 = fmaf(sc, v2.x, a0); a1 = fmaf(sc, v2.y, a1);
      }
      float inv = s_inv[h];
      s_wf[h][ep*2]   = a0*inv;
      s_wf[h][ep*2+1] = a1*inv;
    }
    __syncthreads();
    if (tid < HID){
      const float* v = s_wf[tid >> 6];
      const float* w = Wv + (size_t)(es*64)*HID + tid;
      float a0=0.f,a1=0.f,a2=0.f,a3=0.f;
      #pragma unroll 4
      for (int e = 0; e < 64; e += 4){
        a0 = fmaf(v[e+0], w[(size_t)(e+0)*HID], a0);
        a1 = fmaf(v[e+1], w[(size_t)(e+1)*HID], a1);
        a2 = fmaf(v[e+2], w[(size_t)(e+2)*HID], a2);
        a3 = fmaf(v[e+3], w[(size_t)(e+3)*HID], a3);
      }
      g_pp[((size_t)es*8 + bm)*HID + tid] = (a0+a1)+(a2+a3);
    }
  }

  gsync();

  // ======== phase C: LN + class projection (blocks 0..131) ========
  if (blk < 132){
    float* s_a = (float*)dyn;                 // 640
    float* s_v = (float*)(dyn + 2560);        // 640
    float* red = (float*)(dyn + 5120);        // 1024 floats
    float (*s_r)[16][2] = (float(*)[16][2])(dyn + 9216);  // 64x16x2
    int ct = blk >> 2, b2 = blk & 3;          // 33 ct x 4 b
    #pragma unroll
    for (int m = 0; m < 2; m++){
      int bm = b2*2 + m;
      float a = 0.f;
      if (tid < HID){
        a = bv[tid];
        #pragma unroll
        for (int es = 0; es < 8; es++) a += g_pp[((size_t)es*8 + bm)*HID + tid];
      }
      red[tid] = a; __syncthreads();
      for (int s = 512; s; s >>= 1){ if (tid < s) red[tid] += red[tid+s]; __syncthreads(); }
      float mean = red[0] * (1.f/HID); __syncthreads();
      float d = (tid < HID) ? (a - mean) : 0.f;
      red[tid] = d*d; __syncthreads();
      for (int s = 512; s; s >>= 1){ if (tid < s) red[tid] += red[tid+s]; __syncthreads(); }
      float inv = rsqrtf(red[0]*(1.f/HID) + 1e-5f); __syncthreads();
      float* dst = m ? s_v : s_a;
      if (tid < HID) dst[tid] = d*inv*lng[tid] + lnb[tid];
      __syncthreads();
    }
    int cl = tid & 15, g = tid >> 4;          // 64 e-groups of 10
    int c = ct*16 + cl;
    float aa = 0.f, avv = 0.f;
    if (c < NC){
      const float* wa = Wap + (size_t)(g*10)*NC + c;
      const float* wv = Wvp + (size_t)(g*10)*NC + c;
      #pragma unroll
      for (int j = 0; j < 10; j++){
        int e = g*10 + j;
        aa  = fmaf(s_a[e], wa[(size_t)j*NC], aa);
        avv = fmaf(s_v[e], wv[(size_t)j*NC], avv);
      }
    }
    s_r[g][cl][0] = aa;
    s_r[g][cl][1] = avv;
    __syncthreads();
    if (tid < 16){
      float a = 0.f, v = 0.f;
      #pragma unroll
      for (int g2 = 0; g2 < 64; g2++){ a += s_r[g2][tid][0]; v += s_r[g2][tid][1]; }
      int c2 = ct*16 + tid;
      if (c2 < NC)
        out[(size_t)b2*NC + c2] = 0.5f*((a + bap[c2]) + (v + bvp[c2]));
    }
  }
}

// ---------------- launch ----------------
extern "C" void kernel_launch(void* const* d_in, const int* in_sizes, int n_in,
                              void* d_out, int out_size){
  const float* aud  = (const float*)d_in[0];
  const float* vid  = (const float*)d_in[1];
  const float* atok = (const float*)d_in[2];
  const float* vtok = (const float*)d_in[3];
  const float* btk  = (const float*)d_in[4];
  const float* Wk   = (const float*)d_in[5];
  const float* bk   = (const float*)d_in[6];
  const float* Wq   = (const float*)d_in[7];
  const float* bq   = (const float*)d_in[8];
  const float* Wv   = (const float*)d_in[9];
  const float* bv   = (const float*)d_in[10];
  const float* lng  = (const float*)d_in[11];
  const float* lnb  = (const float*)d_in[12];
  const float* Wap  = (const float*)d_in[13];
  const float* bap  = (const float*)d_in[14];
  const float* Wvp  = (const float*)d_in[15];
  const float* bvp  = (const float*)d_in[16];
  float* out = (float*)d_out;

  const int TAIL_SMEM = 2*HSM;   // 56,320 B -> opt-in attribute (proven)
  cudaFuncSetAttribute(k_tail, cudaFuncAttributeMaxDynamicSharedMemorySize, TAIL_SMEM);

  k_prep<<<FEAT_BLKS + NB*MH, 256>>>(aud, vid, atok, vtok, btk, Wk, bk, Wq, bq);
  k_tail<<<GRIDT, TTHR, TAIL_SMEM>>>(Wv, bv, lng, lnb, Wap, bap, Wvp, bvp, out);
}